// round 3
// baseline (speedup 1.0000x reference)
#include <cuda_runtime.h>
#include <math.h>

#define BATCH 4
#define C 128
#define MID 32
#define HW 64
#define N 4096   // HW*HW

typedef unsigned long long u64;

// ---------------- static device scratch (no runtime allocation) ----------------
__device__ float g_Q[BATCH][C][N];
__device__ float g_V[BATCH][C][N];
__device__ float g_invnorm[BATCH][N];
__device__ float g_wmap[BATCH][N];
__device__ float g_bmap[BATCH][N];
__device__ float g_off[BATCH][N];
__device__ float g_smax[BATCH][N];
__device__ float g_sinv[BATCH][N];
__device__ float g_L[BATCH][N][N];        // logits (256MB)
__device__ float g_psum[BATCH][32][N];
__device__ float g_pmx[BATCH][16][N];
__device__ float g_psm[BATCH][16][N];
__device__ float g_Ymid[BATCH][C][N];

// ---------------- packed f32x2 helpers (sm_103a FFMA2) ----------------
__device__ __forceinline__ void fma2(u64& d, u64 a, u64 b) {
    asm("fma.rn.f32x2 %0, %1, %2, %0;" : "+l"(d) : "l"(a), "l"(b));
}
__device__ __forceinline__ u64 pk(float lo, float hi) {
    u64 r; asm("mov.b64 %0, {%1, %2};" : "=l"(r) : "f"(lo), "f"(hi)); return r;
}
__device__ __forceinline__ float2 upk(u64 v) {
    float2 f; asm("mov.b64 {%0, %1}, %2;" : "=f"(f.x), "=f"(f.y) : "l"(v)); return f;
}

// shared inner-product macro: As2 rows duplicated pairs (256 wide), Bs normal (128 wide)
#define GEMM_INNER(As2, Bs)                                                   \
    _Pragma("unroll")                                                         \
    for (int k = 0; k < 16; k++) {                                            \
        u64 ra2[8], rb2[4];                                                   \
        const u64* pa = (const u64*)&As2[k][ty * 16];                         \
        const u64* pb = (const u64*)&Bs[k][tx * 8];                           \
        _Pragma("unroll") for (int i = 0; i < 8; i++) ra2[i] = pa[i];         \
        _Pragma("unroll") for (int j = 0; j < 4; j++) rb2[j] = pb[j];         \
        _Pragma("unroll") for (int i = 0; i < 8; i++)                         \
            _Pragma("unroll") for (int j = 0; j < 4; j++)                     \
                fma2(acc2[i][j], ra2[i], rb2[j]);                             \
    }

// ============================================================================
// K1: Q = q_w @ x + q_b ; V = v_w @ x + v_b
// ============================================================================
__global__ void __launch_bounds__(256, 2) k1_qv(
        const float* __restrict__ x,
        const float* __restrict__ qw, const float* __restrict__ qb,
        const float* __restrict__ vw, const float* __restrict__ vb) {
    const int b = blockIdx.y;
    const int which = blockIdx.z;
    const float* W = which ? vw : qw;
    const float* bias = which ? vb : qb;
    float* out = which ? &g_V[b][0][0] : &g_Q[b][0][0];
    const int n0 = blockIdx.x * 128;
    const float* xb = x + (size_t)b * C * N;

    __shared__ float As2[16][256];
    __shared__ float Bs[16][128];
    const int tid = threadIdx.x;
    const int tx = tid & 15, ty = tid >> 4;

    u64 acc2[8][4];
#pragma unroll
    for (int i = 0; i < 8; i++)
#pragma unroll
        for (int j = 0; j < 4; j++) acc2[i][j] = 0ull;

    for (int k0 = 0; k0 < 128; k0 += 16) {
        {
            int o = tid >> 1;
            int kb = (tid & 1) * 8;
            float a[8];
            *(float4*)&a[0] = *(const float4*)(W + o * 128 + k0 + kb);
            *(float4*)&a[4] = *(const float4*)(W + o * 128 + k0 + kb + 4);
#pragma unroll
            for (int q = 0; q < 8; q++)
                *(u64*)&As2[kb + q][2 * o] = pk(a[q], a[q]);
        }
        {
            int kk = tid >> 4;
            int nn = (tid & 15) * 8;
            *(float4*)&Bs[kk][nn]     = *(const float4*)(xb + (size_t)(k0 + kk) * N + n0 + nn);
            *(float4*)&Bs[kk][nn + 4] = *(const float4*)(xb + (size_t)(k0 + kk) * N + n0 + nn + 4);
        }
        __syncthreads();
        GEMM_INNER(As2, Bs);
        __syncthreads();
    }
#pragma unroll
    for (int i = 0; i < 8; i++) {
        int o = ty * 8 + i;
        float bo = bias[o];
        float r[8];
#pragma unroll
        for (int j = 0; j < 4; j++) {
            float2 v = upk(acc2[i][j]);
            r[2 * j] = v.x + bo; r[2 * j + 1] = v.y + bo;
        }
        *(float4*)(out + (size_t)o * N + n0 + tx * 8)     = *(float4*)&r[0];
        *(float4*)(out + (size_t)o * N + n0 + tx * 8 + 4) = *(float4*)&r[4];
    }
}

// ============================================================================
// K2: per-token heads + inverse key norm
// ============================================================================
__global__ void k2_heads(const float* __restrict__ lw1w, const float* __restrict__ lw1b,
                         const float* __restrict__ lw2w, const float* __restrict__ lw2b,
                         const float* __restrict__ bw1w, const float* __restrict__ bw1b,
                         const float* __restrict__ bw2w, const float* __restrict__ bw2b) {
    __shared__ float s_lw1[MID][C];
    __shared__ float s_bw1[MID][C];
    const int b = blockIdx.y;
    const int n = blockIdx.x * 256 + threadIdx.x;
    for (int e = threadIdx.x; e < MID * C; e += 256) {
        s_lw1[e / C][e % C] = lw1w[e];
        s_bw1[e / C][e % C] = bw1w[e];
    }
    __syncthreads();

    float hl[MID], hb[MID];
#pragma unroll
    for (int h = 0; h < MID; h++) { hl[h] = 0.f; hb[h] = 0.f; }
    float sq = 0.f;
#pragma unroll 4
    for (int c = 0; c < C; c++) {
        float q = g_Q[b][c][n];
        sq = fmaf(q, q, sq);
#pragma unroll
        for (int h = 0; h < MID; h++) {
            hl[h] = fmaf(s_lw1[h][c], q, hl[h]);
            hb[h] = fmaf(s_bw1[h][c], q, hb[h]);
        }
    }
    float wv = lw2b[0], bv = bw2b[0];
#pragma unroll
    for (int h = 0; h < MID; h++) {
        float t = hl[h] + lw1b[h];
        t = (t >= 0.f) ? t : 0.2f * t;
        wv = fmaf(lw2w[h], t, wv);
        float u = hb[h] + bw1b[h];
        u = (u >= 0.f) ? u : 0.2f * u;
        bv = fmaf(bw2w[h], u, bv);
    }
    g_wmap[b][n] = wv;
    g_bmap[b][n] = bv;
    g_invnorm[b][n] = 1.0f / fmaxf(sqrtf(sq), 1e-4f);
}

// ============================================================================
// K3: symmetric logits (528 tile pairs) + per-row-tile column sums
// ============================================================================
__global__ void __launch_bounds__(256, 2) k3_logits_sym() {
    const int b = blockIdx.y;
    int rem = blockIdx.x;
    int it = 0;
    while (rem >= 32 - it) { rem -= 32 - it; it++; }
    const int jt = it + rem;
    const int n0 = it * 128;
    const int m0 = jt * 128;

    __shared__ float As2[16][256];
    __shared__ float Bs[16][128];
    const int tid = threadIdx.x;
    const int tx = tid & 15, ty = tid >> 4;

    u64 acc2[8][4];
#pragma unroll
    for (int i = 0; i < 8; i++)
#pragma unroll
        for (int j = 0; j < 4; j++) acc2[i][j] = 0ull;

    const int kk = tid >> 4;
    const int cc = (tid & 15) * 8;
    for (int k0 = 0; k0 < 128; k0 += 16) {
        float a[8];
        *(float4*)&a[0] = *(const float4*)&g_Q[b][k0 + kk][n0 + cc];
        *(float4*)&a[4] = *(const float4*)&g_Q[b][k0 + kk][n0 + cc + 4];
#pragma unroll
        for (int q = 0; q < 8; q++)
            *(u64*)&As2[kk][2 * (cc + q)] = pk(a[q], a[q]);
        *(float4*)&Bs[kk][cc]     = *(const float4*)&g_Q[b][k0 + kk][m0 + cc];
        *(float4*)&Bs[kk][cc + 4] = *(const float4*)&g_Q[b][k0 + kk][m0 + cc + 4];
        __syncthreads();
        GEMM_INNER(As2, Bs);
        __syncthreads();
    }

    float acc[8][8];
#pragma unroll
    for (int i = 0; i < 8; i++)
#pragma unroll
        for (int j = 0; j < 4; j++) {
            float2 v = upk(acc2[i][j]);
            acc[i][2 * j] = v.x; acc[i][2 * j + 1] = v.y;
        }

    float invn[8], invm[8];
#pragma unroll
    for (int i = 0; i < 8; i++) {
        invn[i] = g_invnorm[b][n0 + ty * 8 + i];
        invm[i] = g_invnorm[b][m0 + tx * 8 + i];
    }

    // L[n][m] = G * inv[n]
#pragma unroll
    for (int i = 0; i < 8; i++) {
        int n = n0 + ty * 8 + i;
        float inv = invn[i];
        float r[8];
#pragma unroll
        for (int j = 0; j < 8; j++) r[j] = acc[i][j] * inv;
        *(float4*)&g_L[b][n][m0 + tx * 8]     = *(float4*)&r[0];
        *(float4*)&g_L[b][n][m0 + tx * 8 + 4] = *(float4*)&r[4];
    }
    // L[m][n] = G * inv[m]
    if (it != jt) {
#pragma unroll
        for (int j = 0; j < 8; j++) {
            int m = m0 + tx * 8 + j;
            float iv = invm[j];
            float r[8];
#pragma unroll
            for (int i = 0; i < 8; i++) r[i] = acc[i][j] * iv;
            *(float4*)&g_L[b][m][n0 + ty * 8]     = *(float4*)&r[0];
            *(float4*)&g_L[b][m][n0 + ty * 8 + 4] = *(float4*)&r[4];
        }
    }

    // column-sum partials (reuse As2 as scratch)
    __syncthreads();
#pragma unroll
    for (int j = 0; j < 8; j++) {
        float s = 0.f;
#pragma unroll
        for (int i = 0; i < 8; i++) s = fmaf(acc[i][j], invn[i], s);
        As2[ty][tx * 8 + j] = s;
    }
    __syncthreads();
    if (tid < 128) {
        float s = 0.f;
#pragma unroll
        for (int r = 0; r < 16; r++) s += As2[r][tid];
        g_psum[b][it][m0 + tid] = s;
    }
    if (it != jt) {
        __syncthreads();
#pragma unroll
        for (int i = 0; i < 8; i++) {
            float s = 0.f;
#pragma unroll
            for (int j = 0; j < 8; j++) s = fmaf(acc[i][j], invm[j], s);
            As2[tx][ty * 8 + i] = s;
        }
        __syncthreads();
        if (tid < 128) {
            float s = 0.f;
#pragma unroll
            for (int r = 0; r < 16; r++) s += As2[r][tid];
            g_psum[b][jt][n0 + tid] = s;
        }
    }
}

// ============================================================================
// K4b: partial online max/sum-exp of z = l*relu(l+off) over 256-row chunks
// ============================================================================
__global__ void k4b_partial() {
    const int b = blockIdx.z;
    const int chunk = blockIdx.y;
    const int m = blockIdx.x * 256 + threadIdx.x;

    float ps = 0.f;
#pragma unroll
    for (int t = 0; t < 32; t++) ps += g_psum[b][t][m];
    const float mean = ps * (1.0f / N);
    const float off = g_bmap[b][m] - mean * g_wmap[b][m];
    if (chunk == 0) g_off[b][m] = off;

    const int nbase = chunk * 256;
    float mx0 = -1e30f, mx1 = -1e30f, mx2 = -1e30f, mx3 = -1e30f;
    float s0 = 0.f, s1 = 0.f, s2 = 0.f, s3 = 0.f;

#define CHAIN(MX, S, L) { float sp = fmaxf((L) + off, 0.f); float z = (L) * sp; \
    if (z <= MX) { S += __expf(z - MX); } else { S = S * __expf(MX - z) + 1.f; MX = z; } }

#pragma unroll 2
    for (int r = 0; r < 256; r += 4) {
        float l0 = g_L[b][nbase + r + 0][m];
        float l1 = g_L[b][nbase + r + 1][m];
        float l2 = g_L[b][nbase + r + 2][m];
        float l3 = g_L[b][nbase + r + 3][m];
        CHAIN(mx0, s0, l0);
        CHAIN(mx1, s1, l1);
        CHAIN(mx2, s2, l2);
        CHAIN(mx3, s3, l3);
    }
#undef CHAIN
    float M = fmaxf(fmaxf(mx0, mx1), fmaxf(mx2, mx3));
    float S = s0 * __expf(mx0 - M) + s1 * __expf(mx1 - M)
            + s2 * __expf(mx2 - M) + s3 * __expf(mx3 - M);
    g_pmx[b][chunk][m] = M;
    g_psm[b][chunk][m] = S;
}

__global__ void k4c_final() {
    const int b = blockIdx.y;
    const int m = blockIdx.x * 256 + threadIdx.x;
    float M = g_pmx[b][0][m];
    float S = g_psm[b][0][m];
#pragma unroll
    for (int t = 1; t < 16; t++) {
        float m2 = g_pmx[b][t][m], s2 = g_psm[b][t][m];
        float Mn = fmaxf(M, m2);
        S = S * __expf(M - Mn) + s2 * __expf(m2 - Mn);
        M = Mn;
    }
    g_smax[b][m] = M;
    g_sinv[b][m] = 1.0f / S;
}

// ============================================================================
// K5: Y = V @ attn(L), attn on the fly, reg-prefetch pipeline
// ============================================================================
__global__ void __launch_bounds__(256, 2) k5_out() {
    const int b = blockIdx.y;
    const int m0 = blockIdx.x * 128;

    __shared__ float As2[16][256];
    __shared__ float Bs[16][128];
    __shared__ float p_off[128], p_mx[128], p_si[128];
    const int tid = threadIdx.x;
    const int tx = tid & 15, ty = tid >> 4;

    if (tid < 128) {
        int m = m0 + tid;
        p_off[tid] = g_off[b][m];
        p_mx[tid] = g_smax[b][m];
        p_si[tid] = g_sinv[b][m];
    }

    u64 acc2[8][4];
#pragma unroll
    for (int i = 0; i < 8; i++)
#pragma unroll
        for (int j = 0; j < 4; j++) acc2[i][j] = 0ull;

    const int ac = tid >> 1;
    const int akb = (tid & 1) * 8;
    const int bkk = tid >> 4;
    const int bmm = (tid & 15) * 8;

    float av[8], lv[8];
    {
        *(float4*)&av[0] = *(const float4*)&g_V[b][ac][akb];
        *(float4*)&av[4] = *(const float4*)&g_V[b][ac][akb + 4];
        *(float4*)&lv[0] = *(const float4*)&g_L[b][bkk][m0 + bmm];
        *(float4*)&lv[4] = *(const float4*)&g_L[b][bkk][m0 + bmm + 4];
    }
    __syncthreads();

    for (int n0 = 0; n0 < N; n0 += 16) {
#pragma unroll
        for (int q = 0; q < 8; q++)
            *(u64*)&As2[akb + q][2 * ac] = pk(av[q], av[q]);
#pragma unroll
        for (int j = 0; j < 8; j++) {
            int m = bmm + j;
            float l = lv[j];
            float sp = fmaxf(l + p_off[m], 0.f);
            float a;
            if (sp > 0.f)
                a = fmaxf(__expf(l * sp - p_mx[m]) * p_si[m], 1e-8f);
            else
                a = 1e-8f;
            Bs[bkk][m] = a;
        }
        __syncthreads();

        if (n0 + 16 < N) {
            *(float4*)&av[0] = *(const float4*)&g_V[b][ac][n0 + 16 + akb];
            *(float4*)&av[4] = *(const float4*)&g_V[b][ac][n0 + 16 + akb + 4];
            *(float4*)&lv[0] = *(const float4*)&g_L[b][n0 + 16 + bkk][m0 + bmm];
            *(float4*)&lv[4] = *(const float4*)&g_L[b][n0 + 16 + bkk][m0 + bmm + 4];
        }

        GEMM_INNER(As2, Bs);
        __syncthreads();
    }
#pragma unroll
    for (int i = 0; i < 8; i++) {
        int c = ty * 8 + i;
        float r[8];
#pragma unroll
        for (int j = 0; j < 4; j++) {
            float2 v = upk(acc2[i][j]);
            r[2 * j] = v.x; r[2 * j + 1] = v.y;
        }
        *(float4*)&g_Ymid[b][c][m0 + tx * 8]     = *(float4*)&r[0];
        *(float4*)&g_Ymid[b][c][m0 + tx * 8 + 4] = *(float4*)&r[4];
    }
}

// ============================================================================
// K6: conv3x3(SAME) as 9 shifted GEMMs + bias + leaky + residual
// ============================================================================
__global__ void __launch_bounds__(256, 2) k6_conv(
        const float* __restrict__ linw, const float* __restrict__ linb,
        const float* __restrict__ x, float* __restrict__ out) {
    const int b = blockIdx.y;
    const int p0 = blockIdx.x * 128;

    __shared__ float As2[16][256];
    __shared__ float Bs[16][128];
    const int tid = threadIdx.x;
    const int tx = tid & 15, ty = tid >> 4;

    u64 acc2[8][4];
#pragma unroll
    for (int i = 0; i < 8; i++)
#pragma unroll
        for (int j = 0; j < 4; j++) acc2[i][j] = 0ull;

    const int ao = tid >> 1;
    const int akb = (tid & 1) * 8;
    const int bkk = tid >> 4;
    const int bpx = (tid & 15) * 8;

    for (int t = 0; t < 9; t++) {
        const int dh = t / 3 - 1, dw = t % 3 - 1;
        for (int i0 = 0; i0 < 128; i0 += 16) {
#pragma unroll
            for (int q = 0; q < 8; q++) {
                float w = linw[(size_t)(ao * 128 + i0 + akb + q) * 9 + t];
                *(u64*)&As2[akb + q][2 * ao] = pk(w, w);
            }
#pragma unroll
            for (int q = 0; q < 8; q++) {
                int p = p0 + bpx + q;
                int h = p >> 6, w = p & 63;
                int hh = h + dh, ww = w + dw;
                float v = 0.f;
                if (hh >= 0 && hh < HW && ww >= 0 && ww < HW)
                    v = g_Ymid[b][i0 + bkk][(hh << 6) + ww];
                Bs[bkk][bpx + q] = v;
            }
            __syncthreads();
            GEMM_INNER(As2, Bs);
            __syncthreads();
        }
    }
#pragma unroll
    for (int i = 0; i < 8; i++) {
        int o = ty * 8 + i;
        float bo = linb[o];
        size_t base = ((size_t)b * C + o) * N + p0 + tx * 8;
        float acc[8];
#pragma unroll
        for (int j = 0; j < 4; j++) {
            float2 v = upk(acc2[i][j]);
            acc[2 * j] = v.x; acc[2 * j + 1] = v.y;
        }
#pragma unroll
        for (int j = 0; j < 8; j++) {
            float v = acc[j] + bo;
            v = (v >= 0.f) ? v : 0.2f * v;
            out[base + j] = v + x[base + j];
        }
    }
}

// ============================================================================
extern "C" void kernel_launch(void* const* d_in, const int* in_sizes, int n_in,
                              void* d_out, int out_size) {
    const float* x     = (const float*)d_in[0];
    const float* q_w   = (const float*)d_in[1];
    const float* q_b   = (const float*)d_in[2];
    const float* v_w   = (const float*)d_in[3];
    const float* v_b   = (const float*)d_in[4];
    const float* lw1_w = (const float*)d_in[5];
    const float* lw1_b = (const float*)d_in[6];
    const float* lw2_w = (const float*)d_in[7];
    const float* lw2_b = (const float*)d_in[8];
    const float* bw1_w = (const float*)d_in[9];
    const float* bw1_b = (const float*)d_in[10];
    const float* bw2_w = (const float*)d_in[11];
    const float* bw2_b = (const float*)d_in[12];
    const float* lin_w = (const float*)d_in[13];
    const float* lin_b = (const float*)d_in[14];
    float* out = (float*)d_out;

    k1_qv<<<dim3(N / 128, BATCH, 2), 256>>>(x, q_w, q_b, v_w, v_b);
    k2_heads<<<dim3(N / 256, BATCH), 256>>>(lw1_w, lw1_b, lw2_w, lw2_b,
                                            bw1_w, bw1_b, bw2_w, bw2_b);
    k3_logits_sym<<<dim3(528, BATCH), 256>>>();
    k4b_partial<<<dim3(16, 16, BATCH), 256>>>();
    k4c_final<<<dim3(16, BATCH), 256>>>();
    k5_out<<<dim3(N / 128, BATCH), 256>>>();
    k6_conv<<<dim3(N / 128, BATCH), 256>>>(lin_w, lin_b, x, out);
}

// round 5
// speedup vs baseline: 1.1718x; 1.1718x over previous
#include <cuda_runtime.h>
#include <cuda_bf16.h>
#include <cstdint>
#include <math.h>

#define BATCH 4
#define C 128
#define MID 32
#define HW 64
#define N 4096   // HW*HW

// ---------------- static device scratch (no runtime allocation) ----------------
__device__ float g_Q[BATCH][C][N];
__device__ float g_V[BATCH][C][N];
__device__ __nv_bfloat16 g_QThi[BATCH][N][C];   // transposed Q, bf16 hi part
__device__ __nv_bfloat16 g_QTlo[BATCH][N][C];   // transposed Q, bf16 lo part
__device__ float g_invnorm[BATCH][N];
__device__ float g_wmap[BATCH][N];
__device__ float g_bmap[BATCH][N];
__device__ float g_off[BATCH][N];
__device__ float g_smax[BATCH][N];
__device__ float g_sinv[BATCH][N];
__device__ float g_L[BATCH][N][N];        // logits (256MB)
__device__ float g_psum[BATCH][32][N];
__device__ float g_pmx[BATCH][16][N];
__device__ float g_psm[BATCH][16][N];
__device__ float g_Ymid[BATCH][C][N];

// ---------------- warp MMA helpers (baseline PTX, no arch suffix) ----------------
__device__ __forceinline__ uint32_t smem_u32(const void* p) {
    uint32_t a;
    asm("{ .reg .u64 t; cvta.to.shared.u64 t, %1; cvt.u32.u64 %0, t; }" : "=r"(a) : "l"(p));
    return a;
}
__device__ __forceinline__ void ldsm_x4(uint32_t* r, uint32_t addr) {
    asm volatile("ldmatrix.sync.aligned.m8n8.x4.shared.b16 {%0,%1,%2,%3}, [%4];"
                 : "=r"(r[0]), "=r"(r[1]), "=r"(r[2]), "=r"(r[3]) : "r"(addr));
}
__device__ __forceinline__ void mma_bf16(float* d, const uint32_t* a, const uint32_t* b) {
    asm volatile(
        "mma.sync.aligned.m16n8k16.row.col.f32.bf16.bf16.f32 "
        "{%0,%1,%2,%3}, {%4,%5,%6,%7}, {%8,%9}, {%0,%1,%2,%3};"
        : "+f"(d[0]), "+f"(d[1]), "+f"(d[2]), "+f"(d[3])
        : "r"(a[0]), "r"(a[1]), "r"(a[2]), "r"(a[3]), "r"(b[0]), "r"(b[1]));
}

// padded tile row: 128 bf16 data + 8 pad = 136 elems = 272 bytes
#define TPAD 136
#define TILE_BYTES (128 * TPAD * 2)        // 34816
// smem layout for k3: 4 operand tiles, then invn/invm/redA/redB. sD reuses offset 0.
#define OFF_AHI 0
#define OFF_ALO (TILE_BYTES)
#define OFF_BHI (2 * TILE_BYTES)
#define OFF_BLO (3 * TILE_BYTES)
#define OFF_AUX (4 * TILE_BYTES)           // 139264
#define K3_SMEM_BYTES (OFF_AUX + 3072)     // 142336

// ============================================================================
// K1: Q = q_w @ x + q_b ; V = v_w @ x + v_b  (scalar FFMA GEMM, round-2 form)
// ============================================================================
__global__ void k1_qv(const float* __restrict__ x,
                      const float* __restrict__ qw, const float* __restrict__ qb,
                      const float* __restrict__ vw, const float* __restrict__ vb) {
    const int b = blockIdx.y;
    const int which = blockIdx.z;
    const float* W = which ? vw : qw;
    const float* bias = which ? vb : qb;
    float* out = which ? &g_V[b][0][0] : &g_Q[b][0][0];
    const int n0 = blockIdx.x * 128;
    const float* xb = x + (size_t)b * C * N;

    __shared__ float As[16][128];
    __shared__ float Bs[16][128];
    const int tid = threadIdx.x;
    const int tx = tid & 15, ty = tid >> 4;

    float acc[8][8];
#pragma unroll
    for (int i = 0; i < 8; i++)
#pragma unroll
        for (int j = 0; j < 8; j++) acc[i][j] = 0.f;

    for (int k0 = 0; k0 < 128; k0 += 16) {
        {
            int o = tid >> 1;
            int kb = (tid & 1) * 8;
            float4 a0 = *(const float4*)(W + o * 128 + k0 + kb);
            float4 a1 = *(const float4*)(W + o * 128 + k0 + kb + 4);
            As[kb + 0][o] = a0.x; As[kb + 1][o] = a0.y; As[kb + 2][o] = a0.z; As[kb + 3][o] = a0.w;
            As[kb + 4][o] = a1.x; As[kb + 5][o] = a1.y; As[kb + 6][o] = a1.z; As[kb + 7][o] = a1.w;
        }
        {
            int kk = tid >> 4;
            int nn = (tid & 15) * 8;
            *(float4*)&Bs[kk][nn]     = *(const float4*)(xb + (size_t)(k0 + kk) * N + n0 + nn);
            *(float4*)&Bs[kk][nn + 4] = *(const float4*)(xb + (size_t)(k0 + kk) * N + n0 + nn + 4);
        }
        __syncthreads();
#pragma unroll
        for (int kk = 0; kk < 16; kk++) {
            float ra[8], rb[8];
            *(float4*)&ra[0] = *(const float4*)&As[kk][ty * 8];
            *(float4*)&ra[4] = *(const float4*)&As[kk][ty * 8 + 4];
            *(float4*)&rb[0] = *(const float4*)&Bs[kk][tx * 8];
            *(float4*)&rb[4] = *(const float4*)&Bs[kk][tx * 8 + 4];
#pragma unroll
            for (int i = 0; i < 8; i++)
#pragma unroll
                for (int j = 0; j < 8; j++)
                    acc[i][j] = fmaf(ra[i], rb[j], acc[i][j]);
        }
        __syncthreads();
    }
#pragma unroll
    for (int i = 0; i < 8; i++) {
        int o = ty * 8 + i;
        float bo = bias[o];
        float4 r0, r1;
        r0.x = acc[i][0] + bo; r0.y = acc[i][1] + bo; r0.z = acc[i][2] + bo; r0.w = acc[i][3] + bo;
        r1.x = acc[i][4] + bo; r1.y = acc[i][5] + bo; r1.z = acc[i][6] + bo; r1.w = acc[i][7] + bo;
        *(float4*)(out + (size_t)o * N + n0 + tx * 8)     = r0;
        *(float4*)(out + (size_t)o * N + n0 + tx * 8 + 4) = r1;
    }
}

// ============================================================================
// K1t: transpose Q -> QT (bf16 hi/lo split), 32x32 tiles
// ============================================================================
__global__ void k1t_transpose() {
    __shared__ float s[32][33];
    const int b = blockIdx.z;
    const int c0 = blockIdx.y * 32;
    const int n0 = blockIdx.x * 32;
    const int tid = threadIdx.x;
    const int tx = tid & 31, ty = tid >> 5;   // 32 x 8

#pragma unroll
    for (int p = 0; p < 4; p++)
        s[ty + 8 * p][tx] = g_Q[b][c0 + ty + 8 * p][n0 + tx];
    __syncthreads();
#pragma unroll
    for (int p = 0; p < 4; p++) {
        int r = ty + 8 * p;
        float v = s[tx][r];
        __nv_bfloat16 hi = __float2bfloat16(v);
        __nv_bfloat16 lo = __float2bfloat16(v - __bfloat162float(hi));
        g_QThi[b][n0 + r][c0 + tx] = hi;
        g_QTlo[b][n0 + r][c0 + tx] = lo;
    }
}

// ============================================================================
// K2: per-token heads + inverse key norm
// ============================================================================
__global__ void k2_heads(const float* __restrict__ lw1w, const float* __restrict__ lw1b,
                         const float* __restrict__ lw2w, const float* __restrict__ lw2b,
                         const float* __restrict__ bw1w, const float* __restrict__ bw1b,
                         const float* __restrict__ bw2w, const float* __restrict__ bw2b) {
    __shared__ float s_lw1[MID][C];
    __shared__ float s_bw1[MID][C];
    const int b = blockIdx.y;
    const int n = blockIdx.x * 256 + threadIdx.x;
    for (int e = threadIdx.x; e < MID * C; e += 256) {
        s_lw1[e / C][e % C] = lw1w[e];
        s_bw1[e / C][e % C] = bw1w[e];
    }
    __syncthreads();

    float hl[MID], hb[MID];
#pragma unroll
    for (int h = 0; h < MID; h++) { hl[h] = 0.f; hb[h] = 0.f; }
    float sq = 0.f;
#pragma unroll 4
    for (int c = 0; c < C; c++) {
        float q = g_Q[b][c][n];
        sq = fmaf(q, q, sq);
#pragma unroll
        for (int h = 0; h < MID; h++) {
            hl[h] = fmaf(s_lw1[h][c], q, hl[h]);
            hb[h] = fmaf(s_bw1[h][c], q, hb[h]);
        }
    }
    float wv = lw2b[0], bv = bw2b[0];
#pragma unroll
    for (int h = 0; h < MID; h++) {
        float t = hl[h] + lw1b[h];
        t = (t >= 0.f) ? t : 0.2f * t;
        wv = fmaf(lw2w[h], t, wv);
        float u = hb[h] + bw1b[h];
        u = (u >= 0.f) ? u : 0.2f * u;
        bv = fmaf(bw2w[h], u, bv);
    }
    g_wmap[b][n] = wv;
    g_bmap[b][n] = bv;
    g_invnorm[b][n] = 1.0f / fmaxf(sqrtf(sq), 1e-4f);
}

// ============================================================================
// K3 (mma.sync): symmetric logits via bf16 hi/lo 3-pass warp MMA.
// D = Qi^T Qj (128x128, K=C=128), fp32 accumulate.
// Warp grid 2(M)x4(N): each warp = 64x32 = 4 m-tiles(16) x 4 n-tiles(8).
// ============================================================================
__global__ void __launch_bounds__(256, 1) k3_mma() {
    extern __shared__ char smem[];
    const uint32_t sb = smem_u32(smem);
    const int tid = threadIdx.x;
    const int wid = tid >> 5;
    const int lane = tid & 31;

    const int b = blockIdx.y;
    int rem = blockIdx.x;
    int it = 0;
    while (rem >= 32 - it) { rem -= 32 - it; it++; }
    const int jt = it + rem;
    const int n0 = it * 128;
    const int m0 = jt * 128;
    const bool diag = (it == jt);

    // ---- stage 4 (or 2) operand tiles into padded smem ----
    {
        const char* srcs[4] = {
            (const char*)&g_QThi[b][n0][0], (const char*)&g_QTlo[b][n0][0],
            (const char*)&g_QThi[b][m0][0], (const char*)&g_QTlo[b][m0][0] };
        const int ntiles = diag ? 2 : 4;
        for (int t = 0; t < ntiles; t++) {
            const char* src = srcs[t];
            char* dst = smem + t * TILE_BYTES;
            for (int idx = tid; idx < 2048; idx += 256) {
                int row = idx >> 4, ch = idx & 15;
                *(uint4*)(dst + row * (TPAD * 2) + ch * 16) = *(const uint4*)(src + idx * 16);
            }
        }
    }
    // inv arrays
    float* s_invn = (float*)(smem + OFF_AUX);
    float* s_invm = (float*)(smem + OFF_AUX + 512);
    if (tid < 128)      s_invn[tid]       = g_invnorm[b][n0 + tid];
    else                s_invm[tid - 128] = g_invnorm[b][m0 + tid - 128];
    __syncthreads();

    const uint32_t aHiB = sb + OFF_AHI;
    const uint32_t aLoB = sb + OFF_ALO;
    const uint32_t bHiB = diag ? aHiB : (sb + OFF_BHI);
    const uint32_t bLoB = diag ? aLoB : (sb + OFF_BLO);

    const int wm = (wid & 1) * 64;
    const int wn = (wid >> 1) * 32;

    // lane-dependent ldmatrix offsets (bytes)
    const uint32_t aoff = (uint32_t)((lane & 15) * (TPAD * 2) + (lane >> 4) * 16);
    const uint32_t boff = (uint32_t)((((lane >> 4) << 3) + (lane & 7)) * (TPAD * 2)
                                     + ((lane >> 3) & 1) * 16);

    float d[4][4][4];
#pragma unroll
    for (int mt = 0; mt < 4; mt++)
#pragma unroll
        for (int nt = 0; nt < 4; nt++)
#pragma unroll
            for (int q = 0; q < 4; q++) d[mt][nt][q] = 0.f;

#pragma unroll
    for (int ks = 0; ks < 8; ks++) {
        const uint32_t kb2 = ks * 32;   // kb*2 bytes
        uint32_t ah[4][4], al[4][4], bh[2][4], bl[2][4];
#pragma unroll
        for (int mt = 0; mt < 4; mt++) {
            uint32_t rowb = (uint32_t)((wm + mt * 16) * (TPAD * 2)) + kb2 + aoff;
            ldsm_x4(ah[mt], aHiB + rowb);
            ldsm_x4(al[mt], aLoB + rowb);
        }
#pragma unroll
        for (int np = 0; np < 2; np++) {
            uint32_t rowb = (uint32_t)((wn + np * 16) * (TPAD * 2)) + kb2 + boff;
            ldsm_x4(bh[np], bHiB + rowb);
            ldsm_x4(bl[np], bLoB + rowb);
        }
#pragma unroll
        for (int mt = 0; mt < 4; mt++)
#pragma unroll
            for (int np = 0; np < 2; np++)
#pragma unroll
                for (int sub = 0; sub < 2; sub++) {
                    const int nt = np * 2 + sub;
                    mma_bf16(d[mt][nt], ah[mt], &bh[np][sub * 2]);
                    mma_bf16(d[mt][nt], ah[mt], &bl[np][sub * 2]);
                    mma_bf16(d[mt][nt], al[mt], &bh[np][sub * 2]);
                }
    }
    __syncthreads();   // staged tiles dead; reuse smem for sD

    // ---- frags -> sD (128 x 129 f32) ----
    float* sD = (float*)smem;
    {
        const int g = lane >> 2, tg = lane & 3;
#pragma unroll
        for (int mt = 0; mt < 4; mt++) {
#pragma unroll
            for (int nt = 0; nt < 4; nt++) {
                int row0 = wm + mt * 16 + g;
                int col0 = wn + nt * 8 + 2 * tg;
                sD[row0 * 129 + col0]           = d[mt][nt][0];
                sD[row0 * 129 + col0 + 1]       = d[mt][nt][1];
                sD[(row0 + 8) * 129 + col0]     = d[mt][nt][2];
                sD[(row0 + 8) * 129 + col0 + 1] = d[mt][nt][3];
            }
        }
    }
    __syncthreads();

    float* redA = (float*)(smem + OFF_AUX + 1024);
    float* redB = (float*)(smem + OFF_AUX + 2048);

    // main triangle write: L[n0+row][m0+c] = D[row][c]*invn[row]; also psum over rows
    {
        const int row = tid >> 1;
        const int cb = (tid & 1) * 64;
        const float invr = s_invn[row];
        float s2 = 0.f;
        float* dst = &g_L[b][n0 + row][m0];
        for (int c = cb; c < cb + 64; c += 4) {
            float d0 = sD[row * 129 + c + 0];
            float d1 = sD[row * 129 + c + 1];
            float d2 = sD[row * 129 + c + 2];
            float d3 = sD[row * 129 + c + 3];
            s2 += d0 * s_invm[c] + d1 * s_invm[c + 1] + d2 * s_invm[c + 2] + d3 * s_invm[c + 3];
            float4 o; o.x = d0 * invr; o.y = d1 * invr; o.z = d2 * invr; o.w = d3 * invr;
            *(float4*)(dst + c) = o;
        }
        redB[tid] = s2;
    }
    // transposed write: L[m0+col][n0+r] = D[r][col]*invm[col]; psum over cols
    {
        const int col = tid >> 1;
        const int rb = (tid & 1) * 64;
        const float invc = s_invm[col];
        float s1 = 0.f;
        float* dst = &g_L[b][m0 + col][n0];
        for (int r = rb; r < rb + 64; r += 4) {
            float d0 = sD[(r + 0) * 129 + col];
            float d1 = sD[(r + 1) * 129 + col];
            float d2 = sD[(r + 2) * 129 + col];
            float d3 = sD[(r + 3) * 129 + col];
            s1 += d0 * s_invn[r] + d1 * s_invn[r + 1] + d2 * s_invn[r + 2] + d3 * s_invn[r + 3];
            if (!diag) {
                float4 o; o.x = d0 * invc; o.y = d1 * invc; o.z = d2 * invc; o.w = d3 * invc;
                *(float4*)(dst + r) = o;
            }
        }
        redA[tid] = s1;
    }
    __syncthreads();
    if (tid < 128) {
        g_psum[b][it][m0 + tid] = redA[2 * tid] + redA[2 * tid + 1];
        if (!diag)
            g_psum[b][jt][n0 + tid] = redB[2 * tid] + redB[2 * tid + 1];
    }
}

// ============================================================================
// K4b: partial online max/sum-exp of z = l*relu(l+off) over 256-row chunks
// ============================================================================
__global__ void k4b_partial() {
    const int b = blockIdx.z;
    const int chunk = blockIdx.y;
    const int m = blockIdx.x * 256 + threadIdx.x;

    float ps = 0.f;
#pragma unroll
    for (int t = 0; t < 32; t++) ps += g_psum[b][t][m];
    const float mean = ps * (1.0f / N);
    const float off = g_bmap[b][m] - mean * g_wmap[b][m];
    if (chunk == 0) g_off[b][m] = off;

    const int nbase = chunk * 256;
    float mx0 = -1e30f, mx1 = -1e30f, mx2 = -1e30f, mx3 = -1e30f;
    float s0 = 0.f, s1 = 0.f, s2 = 0.f, s3 = 0.f;

#define CHAIN(MX, S, L) { float sp = fmaxf((L) + off, 0.f); float z = (L) * sp; \
    if (z <= MX) { S += __expf(z - MX); } else { S = S * __expf(MX - z) + 1.f; MX = z; } }

#pragma unroll 2
    for (int r = 0; r < 256; r += 4) {
        float l0 = g_L[b][nbase + r + 0][m];
        float l1 = g_L[b][nbase + r + 1][m];
        float l2 = g_L[b][nbase + r + 2][m];
        float l3 = g_L[b][nbase + r + 3][m];
        CHAIN(mx0, s0, l0);
        CHAIN(mx1, s1, l1);
        CHAIN(mx2, s2, l2);
        CHAIN(mx3, s3, l3);
    }
#undef CHAIN
    float M = fmaxf(fmaxf(mx0, mx1), fmaxf(mx2, mx3));
    float S = s0 * __expf(mx0 - M) + s1 * __expf(mx1 - M)
            + s2 * __expf(mx2 - M) + s3 * __expf(mx3 - M);
    g_pmx[b][chunk][m] = M;
    g_psm[b][chunk][m] = S;
}

__global__ void k4c_final() {
    const int b = blockIdx.y;
    const int m = blockIdx.x * 256 + threadIdx.x;
    float M = g_pmx[b][0][m];
    float S = g_psm[b][0][m];
#pragma unroll
    for (int t = 1; t < 16; t++) {
        float m2 = g_pmx[b][t][m], s2 = g_psm[b][t][m];
        float Mn = fmaxf(M, m2);
        S = S * __expf(M - Mn) + s2 * __expf(m2 - Mn);
        M = Mn;
    }
    g_smax[b][m] = M;
    g_sinv[b][m] = 1.0f / S;
}

// ============================================================================
// K5: Y = V @ attn(L), attn on the fly, reg-prefetch pipeline (round-2 form)
// ============================================================================
__global__ void k5_out() {
    const int b = blockIdx.y;
    const int m0 = blockIdx.x * 128;

    __shared__ float As[16][128];
    __shared__ float Bs[16][128];
    __shared__ float p_off[128], p_mx[128], p_si[128];
    const int tid = threadIdx.x;
    const int tx = tid & 15, ty = tid >> 4;

    if (tid < 128) {
        int m = m0 + tid;
        p_off[tid] = g_off[b][m];
        p_mx[tid] = g_smax[b][m];
        p_si[tid] = g_sinv[b][m];
    }

    float acc[8][8];
#pragma unroll
    for (int i = 0; i < 8; i++)
#pragma unroll
        for (int j = 0; j < 8; j++) acc[i][j] = 0.f;

    const int ac = tid >> 1;
    const int akb = (tid & 1) * 8;
    const int bkk = tid >> 4;
    const int bmm = (tid & 15) * 8;

    float av[8], lv[8];
    {
        *(float4*)&av[0] = *(const float4*)&g_V[b][ac][akb];
        *(float4*)&av[4] = *(const float4*)&g_V[b][ac][akb + 4];
        *(float4*)&lv[0] = *(const float4*)&g_L[b][bkk][m0 + bmm];
        *(float4*)&lv[4] = *(const float4*)&g_L[b][bkk][m0 + bmm + 4];
    }
    __syncthreads();

    for (int n0 = 0; n0 < N; n0 += 16) {
        As[akb + 0][ac] = av[0]; As[akb + 1][ac] = av[1];
        As[akb + 2][ac] = av[2]; As[akb + 3][ac] = av[3];
        As[akb + 4][ac] = av[4]; As[akb + 5][ac] = av[5];
        As[akb + 6][ac] = av[6]; As[akb + 7][ac] = av[7];
#pragma unroll
        for (int j = 0; j < 8; j++) {
            int m = bmm + j;
            float l = lv[j];
            float sp = fmaxf(l + p_off[m], 0.f);
            float a;
            if (sp > 0.f)
                a = fmaxf(__expf(l * sp - p_mx[m]) * p_si[m], 1e-8f);
            else
                a = 1e-8f;
            Bs[bkk][m] = a;
        }
        __syncthreads();

        if (n0 + 16 < N) {
            *(float4*)&av[0] = *(const float4*)&g_V[b][ac][n0 + 16 + akb];
            *(float4*)&av[4] = *(const float4*)&g_V[b][ac][n0 + 16 + akb + 4];
            *(float4*)&lv[0] = *(const float4*)&g_L[b][n0 + 16 + bkk][m0 + bmm];
            *(float4*)&lv[4] = *(const float4*)&g_L[b][n0 + 16 + bkk][m0 + bmm + 4];
        }

#pragma unroll
        for (int k = 0; k < 16; k++) {
            float ra[8], rb[8];
            *(float4*)&ra[0] = *(const float4*)&As[k][ty * 8];
            *(float4*)&ra[4] = *(const float4*)&As[k][ty * 8 + 4];
            *(float4*)&rb[0] = *(const float4*)&Bs[k][tx * 8];
            *(float4*)&rb[4] = *(const float4*)&Bs[k][tx * 8 + 4];
#pragma unroll
            for (int i = 0; i < 8; i++)
#pragma unroll
                for (int j = 0; j < 8; j++)
                    acc[i][j] = fmaf(ra[i], rb[j], acc[i][j]);
        }
        __syncthreads();
    }
#pragma unroll
    for (int i = 0; i < 8; i++) {
        int c = ty * 8 + i;
        *(float4*)&g_Ymid[b][c][m0 + tx * 8]     = *(float4*)&acc[i][0];
        *(float4*)&g_Ymid[b][c][m0 + tx * 8 + 4] = *(float4*)&acc[i][4];
    }
}

// ============================================================================
// K6: conv3x3(SAME) as 9 shifted GEMMs + bias + leaky + residual (round-2 form)
// ============================================================================
__global__ void k6_conv(const float* __restrict__ linw, const float* __restrict__ linb,
                        const float* __restrict__ x, float* __restrict__ out) {
    const int b = blockIdx.y;
    const int p0 = blockIdx.x * 128;

    __shared__ float As[16][128];
    __shared__ float Bs[16][128];
    const int tid = threadIdx.x;
    const int tx = tid & 15, ty = tid >> 4;

    float acc[8][8];
#pragma unroll
    for (int i = 0; i < 8; i++)
#pragma unroll
        for (int j = 0; j < 8; j++) acc[i][j] = 0.f;

    const int ao = tid >> 1;
    const int akb = (tid & 1) * 8;
    const int bkk = tid >> 4;
    const int bpx = (tid & 15) * 8;

    for (int t = 0; t < 9; t++) {
        const int dh = t / 3 - 1, dw = t % 3 - 1;
        for (int i0 = 0; i0 < 128; i0 += 16) {
#pragma unroll
            for (int q = 0; q < 8; q++)
                As[akb + q][ao] = linw[(size_t)(ao * 128 + i0 + akb + q) * 9 + t];
#pragma unroll
            for (int q = 0; q < 8; q++) {
                int p = p0 + bpx + q;
                int h = p >> 6, w = p & 63;
                int hh = h + dh, ww = w + dw;
                float v = 0.f;
                if (hh >= 0 && hh < HW && ww >= 0 && ww < HW)
                    v = g_Ymid[b][i0 + bkk][(hh << 6) + ww];
                Bs[bkk][bpx + q] = v;
            }
            __syncthreads();
#pragma unroll
            for (int k = 0; k < 16; k++) {
                float ra[8], rb[8];
                *(float4*)&ra[0] = *(const float4*)&As[k][ty * 8];
                *(float4*)&ra[4] = *(const float4*)&As[k][ty * 8 + 4];
                *(float4*)&rb[0] = *(const float4*)&Bs[k][tx * 8];
                *(float4*)&rb[4] = *(const float4*)&Bs[k][tx * 8 + 4];
#pragma unroll
                for (int i = 0; i < 8; i++)
#pragma unroll
                    for (int j = 0; j < 8; j++)
                        acc[i][j] = fmaf(ra[i], rb[j], acc[i][j]);
            }
            __syncthreads();
        }
    }
#pragma unroll
    for (int i = 0; i < 8; i++) {
        int o = ty * 8 + i;
        float bo = linb[o];
        size_t base = ((size_t)b * C + o) * N + p0 + tx * 8;
#pragma unroll
        for (int j = 0; j < 8; j++) {
            float v = acc[i][j] + bo;
            v = (v >= 0.f) ? v : 0.2f * v;
            out[base + j] = v + x[base + j];
        }
    }
}

// ============================================================================
extern "C" void kernel_launch(void* const* d_in, const int* in_sizes, int n_in,
                              void* d_out, int out_size) {
    const float* x     = (const float*)d_in[0];
    const float* q_w   = (const float*)d_in[1];
    const float* q_b   = (const float*)d_in[2];
    const float* v_w   = (const float*)d_in[3];
    const float* v_b   = (const float*)d_in[4];
    const float* lw1_w = (const float*)d_in[5];
    const float* lw1_b = (const float*)d_in[6];
    const float* lw2_w = (const float*)d_in[7];
    const float* lw2_b = (const float*)d_in[8];
    const float* bw1_w = (const float*)d_in[9];
    const float* bw1_b = (const float*)d_in[10];
    const float* bw2_w = (const float*)d_in[11];
    const float* bw2_b = (const float*)d_in[12];
    const float* lin_w = (const float*)d_in[13];
    const float* lin_b = (const float*)d_in[14];
    float* out = (float*)d_out;

    cudaFuncSetAttribute(k3_mma, cudaFuncAttributeMaxDynamicSharedMemorySize, K3_SMEM_BYTES);

    k1_qv<<<dim3(N / 128, BATCH, 2), 256>>>(x, q_w, q_b, v_w, v_b);
    k1t_transpose<<<dim3(N / 32, C / 32, BATCH), 256>>>();
    k2_heads<<<dim3(N / 256, BATCH), 256>>>(lw1_w, lw1_b, lw2_w, lw2_b,
                                            bw1_w, bw1_b, bw2_w, bw2_b);
    k3_mma<<<dim3(528, BATCH), 256, K3_SMEM_BYTES>>>();
    k4b_partial<<<dim3(16, 16, BATCH), 256>>>();
    k4c_final<<<dim3(16, BATCH), 256>>>();
    k5_out<<<dim3(N / 128, BATCH), 256>>>();
    k6_conv<<<dim3(N / 128, BATCH), 256>>>(lin_w, lin_b, x, out);
}

// round 6
// speedup vs baseline: 1.4821x; 1.2647x over previous
#include <cuda_runtime.h>
#include <cuda_bf16.h>
#include <cstdint>
#include <math.h>

#define BATCH 4
#define C 128
#define MID 32
#define HW 64
#define N 4096   // HW*HW

// ---------------- static device scratch (no runtime allocation) ----------------
__device__ float g_Q[BATCH][C][N];
__device__ float g_V[BATCH][C][N];
__device__ __nv_bfloat16 g_QThi[BATCH][N][C];   // transposed Q, bf16 hi
__device__ __nv_bfloat16 g_QTlo[BATCH][N][C];   // transposed Q, bf16 lo
__device__ __nv_bfloat16 g_Vhi[BATCH][C][N];    // V bf16 hi (K-major for MMA A)
__device__ __nv_bfloat16 g_Vlo[BATCH][C][N];    // V bf16 lo
__device__ float g_invnorm[BATCH][N];
__device__ float g_wmap[BATCH][N];
__device__ float g_bmap[BATCH][N];
__device__ float g_off[BATCH][N];
__device__ float g_smax[BATCH][N];
__device__ float g_sinv[BATCH][N];
__device__ float g_L[BATCH][N][N];        // logits (256MB)
__device__ float g_psum[BATCH][32][N];
__device__ float g_pmx[BATCH][16][N];
__device__ float g_psm[BATCH][16][N];
__device__ float g_Ymid[BATCH][C][N];

// ---------------- warp MMA helpers (baseline PTX, no arch suffix) ----------------
__device__ __forceinline__ uint32_t smem_u32(const void* p) {
    uint32_t a;
    asm("{ .reg .u64 t; cvta.to.shared.u64 t, %1; cvt.u32.u64 %0, t; }" : "=r"(a) : "l"(p));
    return a;
}
__device__ __forceinline__ void ldsm_x4(uint32_t* r, uint32_t addr) {
    asm volatile("ldmatrix.sync.aligned.m8n8.x4.shared.b16 {%0,%1,%2,%3}, [%4];"
                 : "=r"(r[0]), "=r"(r[1]), "=r"(r[2]), "=r"(r[3]) : "r"(addr));
}
__device__ __forceinline__ void mma_bf16(float* d, const uint32_t* a, const uint32_t* b) {
    asm volatile(
        "mma.sync.aligned.m16n8k16.row.col.f32.bf16.bf16.f32 "
        "{%0,%1,%2,%3}, {%4,%5,%6,%7}, {%8,%9}, {%0,%1,%2,%3};"
        : "+f"(d[0]), "+f"(d[1]), "+f"(d[2]), "+f"(d[3])
        : "r"(a[0]), "r"(a[1]), "r"(a[2]), "r"(a[3]), "r"(b[0]), "r"(b[1]));
}

// ---- k3 smem layout (128-wide K tiles, pad 8) ----
#define TPAD 136
#define TILE_BYTES (128 * TPAD * 2)        // 34816
#define OFF_AHI 0
#define OFF_ALO (TILE_BYTES)
#define OFF_BHI (2 * TILE_BYTES)
#define OFF_BLO (3 * TILE_BYTES)
#define OFF_AUX (4 * TILE_BYTES)           // 139264
#define K3_SMEM_BYTES (OFF_AUX + 3072)

// ---- k5 smem layout (64-wide K chunks, pad 8 -> 72 elems = 144B rows) ----
#define KC 64
#define TP5 72
#define T5B (128 * TP5 * 2)                // 18432
#define K5_AHI 0
#define K5_ALO (T5B)
#define K5_BHI (2 * T5B)
#define K5_BLO (3 * T5B)
#define K5_AUX (4 * T5B)                   // 73728
#define K5_SMEM_BYTES (K5_AUX + 1536)      // 75264

// ============================================================================
// K1: Q = q_w @ x + q_b ; V = v_w @ x + v_b  (+ V emitted as bf16 hi/lo)
// ============================================================================
__global__ void k1_qv(const float* __restrict__ x,
                      const float* __restrict__ qw, const float* __restrict__ qb,
                      const float* __restrict__ vw, const float* __restrict__ vb) {
    const int b = blockIdx.y;
    const int which = blockIdx.z;
    const float* W = which ? vw : qw;
    const float* bias = which ? vb : qb;
    float* out = which ? &g_V[b][0][0] : &g_Q[b][0][0];
    const int n0 = blockIdx.x * 128;
    const float* xb = x + (size_t)b * C * N;

    __shared__ float As[16][128];
    __shared__ float Bs[16][128];
    const int tid = threadIdx.x;
    const int tx = tid & 15, ty = tid >> 4;

    float acc[8][8];
#pragma unroll
    for (int i = 0; i < 8; i++)
#pragma unroll
        for (int j = 0; j < 8; j++) acc[i][j] = 0.f;

    for (int k0 = 0; k0 < 128; k0 += 16) {
        {
            int o = tid >> 1;
            int kb = (tid & 1) * 8;
            float4 a0 = *(const float4*)(W + o * 128 + k0 + kb);
            float4 a1 = *(const float4*)(W + o * 128 + k0 + kb + 4);
            As[kb + 0][o] = a0.x; As[kb + 1][o] = a0.y; As[kb + 2][o] = a0.z; As[kb + 3][o] = a0.w;
            As[kb + 4][o] = a1.x; As[kb + 5][o] = a1.y; As[kb + 6][o] = a1.z; As[kb + 7][o] = a1.w;
        }
        {
            int kk = tid >> 4;
            int nn = (tid & 15) * 8;
            *(float4*)&Bs[kk][nn]     = *(const float4*)(xb + (size_t)(k0 + kk) * N + n0 + nn);
            *(float4*)&Bs[kk][nn + 4] = *(const float4*)(xb + (size_t)(k0 + kk) * N + n0 + nn + 4);
        }
        __syncthreads();
#pragma unroll
        for (int kk = 0; kk < 16; kk++) {
            float ra[8], rb[8];
            *(float4*)&ra[0] = *(const float4*)&As[kk][ty * 8];
            *(float4*)&ra[4] = *(const float4*)&As[kk][ty * 8 + 4];
            *(float4*)&rb[0] = *(const float4*)&Bs[kk][tx * 8];
            *(float4*)&rb[4] = *(const float4*)&Bs[kk][tx * 8 + 4];
#pragma unroll
            for (int i = 0; i < 8; i++)
#pragma unroll
                for (int j = 0; j < 8; j++)
                    acc[i][j] = fmaf(ra[i], rb[j], acc[i][j]);
        }
        __syncthreads();
    }
#pragma unroll
    for (int i = 0; i < 8; i++) {
        int o = ty * 8 + i;
        float bo = bias[o];
        float r[8];
#pragma unroll
        for (int j = 0; j < 8; j++) r[j] = acc[i][j] + bo;
        *(float4*)(out + (size_t)o * N + n0 + tx * 8)     = *(float4*)&r[0];
        *(float4*)(out + (size_t)o * N + n0 + tx * 8 + 4) = *(float4*)&r[4];
        if (which) {
            uint32_t whi[4], wlo[4];
#pragma unroll
            for (int p = 0; p < 4; p++) {
                __nv_bfloat16 h0 = __float2bfloat16(r[2 * p]);
                __nv_bfloat16 h1 = __float2bfloat16(r[2 * p + 1]);
                __nv_bfloat16 l0 = __float2bfloat16(r[2 * p] - __bfloat162float(h0));
                __nv_bfloat16 l1 = __float2bfloat16(r[2 * p + 1] - __bfloat162float(h1));
                whi[p] = (uint32_t)__bfloat16_as_ushort(h0) | ((uint32_t)__bfloat16_as_ushort(h1) << 16);
                wlo[p] = (uint32_t)__bfloat16_as_ushort(l0) | ((uint32_t)__bfloat16_as_ushort(l1) << 16);
            }
            uint4 vh; vh.x = whi[0]; vh.y = whi[1]; vh.z = whi[2]; vh.w = whi[3];
            uint4 vl; vl.x = wlo[0]; vl.y = wlo[1]; vl.z = wlo[2]; vl.w = wlo[3];
            *(uint4*)&g_Vhi[b][o][n0 + tx * 8] = vh;
            *(uint4*)&g_Vlo[b][o][n0 + tx * 8] = vl;
        }
    }
}

// ============================================================================
// K1t: transpose Q -> QT (bf16 hi/lo split), 32x32 tiles
// ============================================================================
__global__ void k1t_transpose() {
    __shared__ float s[32][33];
    const int b = blockIdx.z;
    const int c0 = blockIdx.y * 32;
    const int n0 = blockIdx.x * 32;
    const int tid = threadIdx.x;
    const int tx = tid & 31, ty = tid >> 5;   // 32 x 8

#pragma unroll
    for (int p = 0; p < 4; p++)
        s[ty + 8 * p][tx] = g_Q[b][c0 + ty + 8 * p][n0 + tx];
    __syncthreads();
#pragma unroll
    for (int p = 0; p < 4; p++) {
        int r = ty + 8 * p;
        float v = s[tx][r];
        __nv_bfloat16 hi = __float2bfloat16(v);
        __nv_bfloat16 lo = __float2bfloat16(v - __bfloat162float(hi));
        g_QThi[b][n0 + r][c0 + tx] = hi;
        g_QTlo[b][n0 + r][c0 + tx] = lo;
    }
}

// ============================================================================
// K2: per-token heads + inverse key norm
// ============================================================================
__global__ void k2_heads(const float* __restrict__ lw1w, const float* __restrict__ lw1b,
                         const float* __restrict__ lw2w, const float* __restrict__ lw2b,
                         const float* __restrict__ bw1w, const float* __restrict__ bw1b,
                         const float* __restrict__ bw2w, const float* __restrict__ bw2b) {
    __shared__ float s_lw1[MID][C];
    __shared__ float s_bw1[MID][C];
    const int b = blockIdx.y;
    const int n = blockIdx.x * 256 + threadIdx.x;
    for (int e = threadIdx.x; e < MID * C; e += 256) {
        s_lw1[e / C][e % C] = lw1w[e];
        s_bw1[e / C][e % C] = bw1w[e];
    }
    __syncthreads();

    float hl[MID], hb[MID];
#pragma unroll
    for (int h = 0; h < MID; h++) { hl[h] = 0.f; hb[h] = 0.f; }
    float sq = 0.f;
#pragma unroll 4
    for (int c = 0; c < C; c++) {
        float q = g_Q[b][c][n];
        sq = fmaf(q, q, sq);
#pragma unroll
        for (int h = 0; h < MID; h++) {
            hl[h] = fmaf(s_lw1[h][c], q, hl[h]);
            hb[h] = fmaf(s_bw1[h][c], q, hb[h]);
        }
    }
    float wv = lw2b[0], bv = bw2b[0];
#pragma unroll
    for (int h = 0; h < MID; h++) {
        float t = hl[h] + lw1b[h];
        t = (t >= 0.f) ? t : 0.2f * t;
        wv = fmaf(lw2w[h], t, wv);
        float u = hb[h] + bw1b[h];
        u = (u >= 0.f) ? u : 0.2f * u;
        bv = fmaf(bw2w[h], u, bv);
    }
    g_wmap[b][n] = wv;
    g_bmap[b][n] = bv;
    g_invnorm[b][n] = 1.0f / fmaxf(sqrtf(sq), 1e-4f);
}

// ============================================================================
// K3 (mma.sync): symmetric logits via bf16 hi/lo 3-pass warp MMA (round-5 form)
// ============================================================================
__global__ void __launch_bounds__(256, 1) k3_mma() {
    extern __shared__ char smem[];
    const uint32_t sb = smem_u32(smem);
    const int tid = threadIdx.x;
    const int wid = tid >> 5;
    const int lane = tid & 31;

    const int b = blockIdx.y;
    int rem = blockIdx.x;
    int it = 0;
    while (rem >= 32 - it) { rem -= 32 - it; it++; }
    const int jt = it + rem;
    const int n0 = it * 128;
    const int m0 = jt * 128;
    const bool diag = (it == jt);

    {
        const char* srcs[4] = {
            (const char*)&g_QThi[b][n0][0], (const char*)&g_QTlo[b][n0][0],
            (const char*)&g_QThi[b][m0][0], (const char*)&g_QTlo[b][m0][0] };
        const int ntiles = diag ? 2 : 4;
        for (int t = 0; t < ntiles; t++) {
            const char* src = srcs[t];
            char* dst = smem + t * TILE_BYTES;
            for (int idx = tid; idx < 2048; idx += 256) {
                int row = idx >> 4, ch = idx & 15;
                *(uint4*)(dst + row * (TPAD * 2) + ch * 16) = *(const uint4*)(src + idx * 16);
            }
        }
    }
    float* s_invn = (float*)(smem + OFF_AUX);
    float* s_invm = (float*)(smem + OFF_AUX + 512);
    if (tid < 128)      s_invn[tid]       = g_invnorm[b][n0 + tid];
    else                s_invm[tid - 128] = g_invnorm[b][m0 + tid - 128];
    __syncthreads();

    const uint32_t aHiB = sb + OFF_AHI;
    const uint32_t aLoB = sb + OFF_ALO;
    const uint32_t bHiB = diag ? aHiB : (sb + OFF_BHI);
    const uint32_t bLoB = diag ? aLoB : (sb + OFF_BLO);

    const int wm = (wid & 1) * 64;
    const int wn = (wid >> 1) * 32;
    const uint32_t aoff = (uint32_t)((lane & 15) * (TPAD * 2) + (lane >> 4) * 16);
    const uint32_t boff = (uint32_t)((((lane >> 4) << 3) + (lane & 7)) * (TPAD * 2)
                                     + ((lane >> 3) & 1) * 16);

    float d[4][4][4];
#pragma unroll
    for (int mt = 0; mt < 4; mt++)
#pragma unroll
        for (int nt = 0; nt < 4; nt++)
#pragma unroll
            for (int q = 0; q < 4; q++) d[mt][nt][q] = 0.f;

#pragma unroll
    for (int ks = 0; ks < 8; ks++) {
        const uint32_t kb2 = ks * 32;
        uint32_t ah[4][4], al[4][4], bh[2][4], bl[2][4];
#pragma unroll
        for (int mt = 0; mt < 4; mt++) {
            uint32_t rowb = (uint32_t)((wm + mt * 16) * (TPAD * 2)) + kb2 + aoff;
            ldsm_x4(ah[mt], aHiB + rowb);
            ldsm_x4(al[mt], aLoB + rowb);
        }
#pragma unroll
        for (int np = 0; np < 2; np++) {
            uint32_t rowb = (uint32_t)((wn + np * 16) * (TPAD * 2)) + kb2 + boff;
            ldsm_x4(bh[np], bHiB + rowb);
            ldsm_x4(bl[np], bLoB + rowb);
        }
#pragma unroll
        for (int mt = 0; mt < 4; mt++)
#pragma unroll
            for (int np = 0; np < 2; np++)
#pragma unroll
                for (int sub = 0; sub < 2; sub++) {
                    const int nt = np * 2 + sub;
                    mma_bf16(d[mt][nt], ah[mt], &bh[np][sub * 2]);
                    mma_bf16(d[mt][nt], ah[mt], &bl[np][sub * 2]);
                    mma_bf16(d[mt][nt], al[mt], &bh[np][sub * 2]);
                }
    }
    __syncthreads();

    float* sD = (float*)smem;
    {
        const int g = lane >> 2, tg = lane & 3;
#pragma unroll
        for (int mt = 0; mt < 4; mt++) {
#pragma unroll
            for (int nt = 0; nt < 4; nt++) {
                int row0 = wm + mt * 16 + g;
                int col0 = wn + nt * 8 + 2 * tg;
                sD[row0 * 129 + col0]           = d[mt][nt][0];
                sD[row0 * 129 + col0 + 1]       = d[mt][nt][1];
                sD[(row0 + 8) * 129 + col0]     = d[mt][nt][2];
                sD[(row0 + 8) * 129 + col0 + 1] = d[mt][nt][3];
            }
        }
    }
    __syncthreads();

    float* redA = (float*)(smem + OFF_AUX + 1024);
    float* redB = (float*)(smem + OFF_AUX + 2048);

    {
        const int row = tid >> 1;
        const int cb = (tid & 1) * 64;
        const float invr = s_invn[row];
        float s2 = 0.f;
        float* dst = &g_L[b][n0 + row][m0];
        for (int c = cb; c < cb + 64; c += 4) {
            float d0 = sD[row * 129 + c + 0];
            float d1 = sD[row * 129 + c + 1];
            float d2 = sD[row * 129 + c + 2];
            float d3 = sD[row * 129 + c + 3];
            s2 += d0 * s_invm[c] + d1 * s_invm[c + 1] + d2 * s_invm[c + 2] + d3 * s_invm[c + 3];
            float4 o; o.x = d0 * invr; o.y = d1 * invr; o.z = d2 * invr; o.w = d3 * invr;
            *(float4*)(dst + c) = o;
        }
        redB[tid] = s2;
    }
    {
        const int col = tid >> 1;
        const int rb = (tid & 1) * 64;
        const float invc = s_invm[col];
        float s1 = 0.f;
        float* dst = &g_L[b][m0 + col][n0];
        for (int r = rb; r < rb + 64; r += 4) {
            float d0 = sD[(r + 0) * 129 + col];
            float d1 = sD[(r + 1) * 129 + col];
            float d2 = sD[(r + 2) * 129 + col];
            float d3 = sD[(r + 3) * 129 + col];
            s1 += d0 * s_invn[r] + d1 * s_invn[r + 1] + d2 * s_invn[r + 2] + d3 * s_invn[r + 3];
            if (!diag) {
                float4 o; o.x = d0 * invc; o.y = d1 * invc; o.z = d2 * invc; o.w = d3 * invc;
                *(float4*)(dst + r) = o;
            }
        }
        redA[tid] = s1;
    }
    __syncthreads();
    if (tid < 128) {
        g_psum[b][it][m0 + tid] = redA[2 * tid] + redA[2 * tid + 1];
        if (!diag)
            g_psum[b][jt][n0 + tid] = redB[2 * tid] + redB[2 * tid + 1];
    }
}

// ============================================================================
// K4b / K4c: column softmax stats (round-2 form)
// ============================================================================
__global__ void k4b_partial() {
    const int b = blockIdx.z;
    const int chunk = blockIdx.y;
    const int m = blockIdx.x * 256 + threadIdx.x;

    float ps = 0.f;
#pragma unroll
    for (int t = 0; t < 32; t++) ps += g_psum[b][t][m];
    const float mean = ps * (1.0f / N);
    const float off = g_bmap[b][m] - mean * g_wmap[b][m];
    if (chunk == 0) g_off[b][m] = off;

    const int nbase = chunk * 256;
    float mx0 = -1e30f, mx1 = -1e30f, mx2 = -1e30f, mx3 = -1e30f;
    float s0 = 0.f, s1 = 0.f, s2 = 0.f, s3 = 0.f;

#define CHAIN(MX, S, L) { float sp = fmaxf((L) + off, 0.f); float z = (L) * sp; \
    if (z <= MX) { S += __expf(z - MX); } else { S = S * __expf(MX - z) + 1.f; MX = z; } }

#pragma unroll 2
    for (int r = 0; r < 256; r += 4) {
        float l0 = g_L[b][nbase + r + 0][m];
        float l1 = g_L[b][nbase + r + 1][m];
        float l2 = g_L[b][nbase + r + 2][m];
        float l3 = g_L[b][nbase + r + 3][m];
        CHAIN(mx0, s0, l0);
        CHAIN(mx1, s1, l1);
        CHAIN(mx2, s2, l2);
        CHAIN(mx3, s3, l3);
    }
#undef CHAIN
    float M = fmaxf(fmaxf(mx0, mx1), fmaxf(mx2, mx3));
    float S = s0 * __expf(mx0 - M) + s1 * __expf(mx1 - M)
            + s2 * __expf(mx2 - M) + s3 * __expf(mx3 - M);
    g_pmx[b][chunk][m] = M;
    g_psm[b][chunk][m] = S;
}

__global__ void k4c_final() {
    const int b = blockIdx.y;
    const int m = blockIdx.x * 256 + threadIdx.x;
    float M = g_pmx[b][0][m];
    float S = g_psm[b][0][m];
#pragma unroll
    for (int t = 1; t < 16; t++) {
        float m2 = g_pmx[b][t][m], s2 = g_psm[b][t][m];
        float Mn = fmaxf(M, m2);
        S = S * __expf(M - Mn) + s2 * __expf(m2 - Mn);
        M = Mn;
    }
    g_smax[b][m] = M;
    g_sinv[b][m] = 1.0f / S;
}

// ============================================================================
// K5 (mma.sync): Y = V @ attn(L) via bf16 hi/lo 3-pass warp MMA.
// Output tile 128(c) x 128(m), K = 4096 in 64-wide chunks.
// ============================================================================
__global__ void __launch_bounds__(256, 1) k5_mma() {
    extern __shared__ char smem[];
    const uint32_t sb = smem_u32(smem);
    const int tid = threadIdx.x;
    const int wid = tid >> 5;
    const int lane = tid & 31;
    const int b = blockIdx.y;
    const int m0 = blockIdx.x * 128;

    float* p_off = (float*)(smem + K5_AUX);
    float* p_mx  = (float*)(smem + K5_AUX + 512);
    float* p_si  = (float*)(smem + K5_AUX + 1024);
    if (tid < 128) {
        int m = m0 + tid;
        p_off[tid] = g_off[b][m];
        p_mx[tid]  = g_smax[b][m];
        p_si[tid]  = g_sinv[b][m];
    }
    __syncthreads();

    const int wm = (wid & 1) * 64;
    const int wn = (wid >> 1) * 32;
    const uint32_t aoff = (uint32_t)((lane & 15) * (TP5 * 2) + (lane >> 4) * 16);
    const uint32_t boff = (uint32_t)((((lane >> 4) << 3) + (lane & 7)) * (TP5 * 2)
                                     + ((lane >> 3) & 1) * 16);

    // B-staging thread mapping: 4 m-cols x 8 k-rows per thread
    const int mm0 = (tid & 31) * 4;
    const int kk0 = (tid >> 5) * 8;

    float d[4][4][4];
#pragma unroll
    for (int mt = 0; mt < 4; mt++)
#pragma unroll
        for (int nt = 0; nt < 4; nt++)
#pragma unroll
            for (int q = 0; q < 4; q++) d[mt][nt][q] = 0.f;

    for (int n0 = 0; n0 < N; n0 += KC) {
        // ---- stage A: copy V hi/lo bf16 tiles [128 c][64 k] ----
        for (int i = tid; i < 2048; i += 256) {
            int t = i >> 10;            // 0=hi,1=lo
            int r = (i >> 3) & 127;
            int q = i & 7;
            const uint4* src = t ? (const uint4*)&g_Vlo[b][r][n0]
                                 : (const uint4*)&g_Vhi[b][r][n0];
            *(uint4*)(smem + t * T5B + r * (TP5 * 2) + q * 16) = src[q];
        }
        // ---- stage B: attn(L) -> bf16 hi/lo tiles [128 m][64 k] ----
        {
            uint32_t whi[4][4], wlo[4][4];
#pragma unroll
            for (int j = 0; j < 4; j++)
#pragma unroll
                for (int p = 0; p < 4; p++) { whi[j][p] = 0u; wlo[j][p] = 0u; }
#pragma unroll
            for (int kk = 0; kk < 8; kk++) {
                float4 l4 = *(const float4*)&g_L[b][n0 + kk0 + kk][m0 + mm0];
                float ls[4] = {l4.x, l4.y, l4.z, l4.w};
#pragma unroll
                for (int j = 0; j < 4; j++) {
                    int m = mm0 + j;
                    float l = ls[j];
                    float sp = fmaxf(l + p_off[m], 0.f);
                    float a;
                    if (sp > 0.f)
                        a = fmaxf(__expf(l * sp - p_mx[m]) * p_si[m], 1e-8f);
                    else
                        a = 1e-8f;
                    __nv_bfloat16 h = __float2bfloat16(a);
                    __nv_bfloat16 lo = __float2bfloat16(a - __bfloat162float(h));
                    uint32_t sh = (uint32_t)(kk & 1) * 16;
                    whi[j][kk >> 1] |= (uint32_t)__bfloat16_as_ushort(h) << sh;
                    wlo[j][kk >> 1] |= (uint32_t)__bfloat16_as_ushort(lo) << sh;
                }
            }
#pragma unroll
            for (int j = 0; j < 4; j++) {
                uint4 vh; vh.x = whi[j][0]; vh.y = whi[j][1]; vh.z = whi[j][2]; vh.w = whi[j][3];
                uint4 vl; vl.x = wlo[j][0]; vl.y = wlo[j][1]; vl.z = wlo[j][2]; vl.w = wlo[j][3];
                *(uint4*)(smem + K5_BHI + (mm0 + j) * (TP5 * 2) + kk0 * 2) = vh;
                *(uint4*)(smem + K5_BLO + (mm0 + j) * (TP5 * 2) + kk0 * 2) = vl;
            }
        }
        __syncthreads();

        // ---- MMA over this chunk: 4 k-steps ----
#pragma unroll
        for (int ks = 0; ks < 4; ks++) {
            const uint32_t kb2 = ks * 32;
            uint32_t ah[4][4], al[4][4], bh[2][4], bl[2][4];
#pragma unroll
            for (int mt = 0; mt < 4; mt++) {
                uint32_t rowb = (uint32_t)((wm + mt * 16) * (TP5 * 2)) + kb2 + aoff;
                ldsm_x4(ah[mt], sb + K5_AHI + rowb);
                ldsm_x4(al[mt], sb + K5_ALO + rowb);
            }
#pragma unroll
            for (int np = 0; np < 2; np++) {
                uint32_t rowb = (uint32_t)((wn + np * 16) * (TP5 * 2)) + kb2 + boff;
                ldsm_x4(bh[np], sb + K5_BHI + rowb);
                ldsm_x4(bl[np], sb + K5_BLO + rowb);
            }
#pragma unroll
            for (int mt = 0; mt < 4; mt++)
#pragma unroll
                for (int np = 0; np < 2; np++)
#pragma unroll
                    for (int sub = 0; sub < 2; sub++) {
                        const int nt = np * 2 + sub;
                        mma_bf16(d[mt][nt], ah[mt], &bh[np][sub * 2]);
                        mma_bf16(d[mt][nt], ah[mt], &bl[np][sub * 2]);
                        mma_bf16(d[mt][nt], al[mt], &bh[np][sub * 2]);
                    }
        }
        __syncthreads();
    }

    // ---- epilogue: fragments -> g_Ymid ----
    {
        const int g = lane >> 2, tg = lane & 3;
#pragma unroll
        for (int mt = 0; mt < 4; mt++) {
#pragma unroll
            for (int nt = 0; nt < 4; nt++) {
                int row0 = wm + mt * 16 + g;
                int col0 = m0 + wn + nt * 8 + 2 * tg;
                float2 v0; v0.x = d[mt][nt][0]; v0.y = d[mt][nt][1];
                float2 v1; v1.x = d[mt][nt][2]; v1.y = d[mt][nt][3];
                *(float2*)&g_Ymid[b][row0][col0]     = v0;
                *(float2*)&g_Ymid[b][row0 + 8][col0] = v1;
            }
        }
    }
}

// ============================================================================
// K6: conv3x3(SAME) as 9 shifted GEMMs + bias + leaky + residual (round-2 form)
// ============================================================================
__global__ void k6_conv(const float* __restrict__ linw, const float* __restrict__ linb,
                        const float* __restrict__ x, float* __restrict__ out) {
    const int b = blockIdx.y;
    const int p0 = blockIdx.x * 128;

    __shared__ float As[16][128];
    __shared__ float Bs[16][128];
    const int tid = threadIdx.x;
    const int tx = tid & 15, ty = tid >> 4;

    float acc[8][8];
#pragma unroll
    for (int i = 0; i < 8; i++)
#pragma unroll
        for (int j = 0; j < 8; j++) acc[i][j] = 0.f;

    const int ao = tid >> 1;
    const int akb = (tid & 1) * 8;
    const int bkk = tid >> 4;
    const int bpx = (tid & 15) * 8;

    for (int t = 0; t < 9; t++) {
        const int dh = t / 3 - 1, dw = t % 3 - 1;
        for (int i0 = 0; i0 < 128; i0 += 16) {
#pragma unroll
            for (int q = 0; q < 8; q++)
                As[akb + q][ao] = linw[(size_t)(ao * 128 + i0 + akb + q) * 9 + t];
#pragma unroll
            for (int q = 0; q < 8; q++) {
                int p = p0 + bpx + q;
                int h = p >> 6, w = p & 63;
                int hh = h + dh, ww = w + dw;
                float v = 0.f;
                if (hh >= 0 && hh < HW && ww >= 0 && ww < HW)
                    v = g_Ymid[b][i0 + bkk][(hh << 6) + ww];
                Bs[bkk][bpx + q] = v;
            }
            __syncthreads();
#pragma unroll
            for (int k = 0; k < 16; k++) {
                float ra[8], rb[8];
                *(float4*)&ra[0] = *(const float4*)&As[k][ty * 8];
                *(float4*)&ra[4] = *(const float4*)&As[k][ty * 8 + 4];
                *(float4*)&rb[0] = *(const float4*)&Bs[k][tx * 8];
                *(float4*)&rb[4] = *(const float4*)&Bs[k][tx * 8 + 4];
#pragma unroll
                for (int i = 0; i < 8; i++)
#pragma unroll
                    for (int j = 0; j < 8; j++)
                        acc[i][j] = fmaf(ra[i], rb[j], acc[i][j]);
            }
            __syncthreads();
        }
    }
#pragma unroll
    for (int i = 0; i < 8; i++) {
        int o = ty * 8 + i;
        float bo = linb[o];
        size_t base = ((size_t)b * C + o) * N + p0 + tx * 8;
#pragma unroll
        for (int j = 0; j < 8; j++) {
            float v = acc[i][j] + bo;
            v = (v >= 0.f) ? v : 0.2f * v;
            out[base + j] = v + x[base + j];
        }
    }
}

// ============================================================================
extern "C" void kernel_launch(void* const* d_in, const int* in_sizes, int n_in,
                              void* d_out, int out_size) {
    const float* x     = (const float*)d_in[0];
    const float* q_w   = (const float*)d_in[1];
    const float* q_b   = (const float*)d_in[2];
    const float* v_w   = (const float*)d_in[3];
    const float* v_b   = (const float*)d_in[4];
    const float* lw1_w = (const float*)d_in[5];
    const float* lw1_b = (const float*)d_in[6];
    const float* lw2_w = (const float*)d_in[7];
    const float* lw2_b = (const float*)d_in[8];
    const float* bw1_w = (const float*)d_in[9];
    const float* bw1_b = (const float*)d_in[10];
    const float* bw2_w = (const float*)d_in[11];
    const float* bw2_b = (const float*)d_in[12];
    const float* lin_w = (const float*)d_in[13];
    const float* lin_b = (const float*)d_in[14];
    float* out = (float*)d_out;

    cudaFuncSetAttribute(k3_mma, cudaFuncAttributeMaxDynamicSharedMemorySize, K3_SMEM_BYTES);
    cudaFuncSetAttribute(k5_mma, cudaFuncAttributeMaxDynamicSharedMemorySize, K5_SMEM_BYTES);

    k1_qv<<<dim3(N / 128, BATCH, 2), 256>>>(x, q_w, q_b, v_w, v_b);
    k1t_transpose<<<dim3(N / 32, C / 32, BATCH), 256>>>();
    k2_heads<<<dim3(N / 256, BATCH), 256>>>(lw1_w, lw1_b, lw2_w, lw2_b,
                                            bw1_w, bw1_b, bw2_w, bw2_b);
    k3_mma<<<dim3(528, BATCH), 256, K3_SMEM_BYTES>>>();
    k4b_partial<<<dim3(16, 16, BATCH), 256>>>();
    k4c_final<<<dim3(16, BATCH), 256>>>();
    k5_mma<<<dim3(N / 128, BATCH), 256, K5_SMEM_BYTES>>>();
    k6_conv<<<dim3(N / 128, BATCH), 256>>>(lin_w, lin_b, x, out);
}